// round 13
// baseline (speedup 1.0000x reference)
#include <cuda_runtime.h>
#include <cuda_fp16.h>
#include <cstdint>
#include <cstddef>

// ============================================================================
// VAE_gamma on GB300. GEMMs: mma.sync m16n8k16.f16 (f32 acc) Markidis split.
// Encoder/heads: 3 products (~fp32 accurate -> sampler decisions exact).
// Decoder: 1 product (fp16 weights x fp16 activations, ~2.2e-4 on recon).
// Gamma sampler fused into the heads-GEMM epilogue. Single batched prep.
// ============================================================================

#define BATCHN   8192
#define LATENT   64
#define KROUNDS  24
#define GAMMA_N  524288u

// ---------------------------------------------------------------------------
// Scratch (half hi/lo planes)
// ---------------------------------------------------------------------------
__device__ alignas(16) __half g_xh [8192 * 2048];
__device__ alignas(16) __half g_xl [8192 * 2048];
__device__ alignas(16) __half g_b0h[8192 * 2048];
__device__ alignas(16) __half g_b0l[8192 * 2048];
__device__ alignas(16) __half g_b1h[8192 * 2048];
__device__ alignas(16) __half g_b1l[8192 * 2048];
__device__ alignas(16) __half g_zh [8192 * 64];
__device__ alignas(16) __half g_wh [12976128];
__device__ alignas(16) __half g_wl [12976128];
__device__ float g_bh [128];

#define OW1  0u                         // [1024][2048]
#define OW2  (OW1 + 2097152u)           // [1024][1024]
#define OW3  (OW2 + 1048576u)           // [2048][1024]
#define OWH  (OW3 + 2097152u)           // [128][2048]
#define OW4  (OWH + 262144u)            // [2048][64]
#define OW5  (OW4 + 131072u)            // [1024][2048]
#define OW6  (OW5 + 2097152u)           // [1024][1024]
#define OW7  (OW6 + 1048576u)           // [4096][1024]

// ---------------------------------------------------------------------------
// Threefry-2x32 (JAX partitionable mode)
// ---------------------------------------------------------------------------
constexpr unsigned rotlc(unsigned x, int r) { return (x << r) | (x >> (32 - r)); }
constexpr unsigned long long tf_const(unsigned k0, unsigned k1,
                                      unsigned x0, unsigned x1) {
    unsigned kx = k0 ^ k1 ^ 0x1BD11BDAu;
    unsigned ks[3] = {k0, k1, kx};
    const int R0[4] = {13, 15, 26, 6};
    const int R1[4] = {17, 29, 16, 24};
    x0 += k0; x1 += k1;
    for (int i = 0; i < 5; i++) {
        const int* rr = (i % 2 == 0) ? R0 : R1;
        for (int j = 0; j < 4; j++) { x0 += x1; x1 = rotlc(x1, rr[j]); x1 ^= x0; }
        x0 += ks[(i + 1) % 3];
        x1 += ks[(i + 2) % 3] + (unsigned)(i + 1);
    }
    return ((unsigned long long)x0 << 32) | x1;
}
constexpr unsigned long long SPN = tf_const(0u, 42u, 0u, 0u);
constexpr unsigned long long SPU = tf_const(0u, 42u, 0u, 1u);
constexpr unsigned KEY_N0 = (unsigned)(SPN >> 32);
constexpr unsigned KEY_N1 = (unsigned)(SPN & 0xFFFFFFFFu);
constexpr unsigned KEY_U0 = (unsigned)(SPU >> 32);
constexpr unsigned KEY_U1 = (unsigned)(SPU & 0xFFFFFFFFu);

__device__ __forceinline__ uint32_t rotl32(uint32_t x, int r) {
    return __funnelshift_l(x, x, r);
}
__device__ __forceinline__ void tf2x32(uint32_t k0, uint32_t k1,
                                       uint32_t x0, uint32_t x1,
                                       uint32_t& y0, uint32_t& y1) {
    uint32_t kx = k0 ^ k1 ^ 0x1BD11BDAu;
    x0 += k0; x1 += k1;
#define TF_RND(r) { x0 += x1; x1 = rotl32(x1, r); x1 ^= x0; }
    TF_RND(13) TF_RND(15) TF_RND(26) TF_RND(6)   x0 += k1; x1 += kx + 1u;
    TF_RND(17) TF_RND(29) TF_RND(16) TF_RND(24)  x0 += kx; x1 += k0 + 2u;
    TF_RND(13) TF_RND(15) TF_RND(26) TF_RND(6)   x0 += k0; x1 += k1 + 3u;
    TF_RND(17) TF_RND(29) TF_RND(16) TF_RND(24)  x0 += k1; x1 += kx + 4u;
    TF_RND(13) TF_RND(15) TF_RND(26) TF_RND(6)   x0 += kx; x1 += k0 + 5u;
#undef TF_RND
    y0 = x0; y1 = x1;
}
__device__ __forceinline__ uint32_t gamma_bits(uint32_t k0, uint32_t k1,
                                               uint32_t idx) {
    uint32_t y0, y1;
    tf2x32(k0, k1, 0u, idx, y0, y1);
    return y0 ^ y1;
}
__device__ __forceinline__ float bits_to_u01(uint32_t bits) {
    return __uint_as_float((bits >> 9) | 0x3F800000u) - 1.0f;
}
__device__ __forceinline__ float erfinv_xla(float x) {
    float w = -log1pf(-__fmul_rn(x, x));
    float p;
    if (w < 5.0f) {
        w = __fadd_rn(w, -2.5f);
        p = 2.81022636e-08f;
        p = __fadd_rn(__fmul_rn(p, w),  3.43273939e-07f);
        p = __fadd_rn(__fmul_rn(p, w), -3.5233877e-06f);
        p = __fadd_rn(__fmul_rn(p, w), -4.39150654e-06f);
        p = __fadd_rn(__fmul_rn(p, w),  0.00021858087f);
        p = __fadd_rn(__fmul_rn(p, w), -0.00125372503f);
        p = __fadd_rn(__fmul_rn(p, w), -0.00417768164f);
        p = __fadd_rn(__fmul_rn(p, w),  0.246640727f);
        p = __fadd_rn(__fmul_rn(p, w),  1.50140941f);
    } else {
        w = __fadd_rn(__fsqrt_rn(w), -3.0f);
        p = -0.000200214257f;
        p = __fadd_rn(__fmul_rn(p, w),  0.000100950558f);
        p = __fadd_rn(__fmul_rn(p, w),  0.00134934322f);
        p = __fadd_rn(__fmul_rn(p, w), -0.00367342844f);
        p = __fadd_rn(__fmul_rn(p, w),  0.00573950773f);
        p = __fadd_rn(__fmul_rn(p, w), -0.0076224613f);
        p = __fadd_rn(__fmul_rn(p, w),  0.00943887047f);
        p = __fadd_rn(__fmul_rn(p, w),  1.00167406f);
        p = __fadd_rn(__fmul_rn(p, w),  2.83297682f);
    }
    return __fmul_rn(p, x);
}
__device__ __forceinline__ float softplusf(float x) {
    return __fadd_rn(fmaxf(x, 0.0f), log1pf(expf(-fabsf(x))));
}

// Sampler for one element (identical math/order to reference path).
__device__ __forceinline__ void gamma_one(float preA, float preB, uint32_t i,
                                          float& out_al, float& out_be,
                                          float& out_zv) {
    float al = __fadd_rn(1e-6f, softplusf(preA));
    float be = __fadd_rn(1e-6f, softplusf(preB));

    float d  = __fadd_rn(__fadd_rn(al, 1.0f), -(1.0f / 3.0f));
    float cc = __fdiv_rn(1.0f, __fsqrt_rn(__fmul_rn(9.0f, d)));

    const float LO     = -0.99999994f;
    const float SPAN_N = 2.0f;
    const float UMIN   = 1e-7f;
    const float SPAN_U = 1.0f - 1e-7f;
    const float SQRT2  = 1.41421356f;

    float eps_s = 0.0f, u_s = 0.0f, eps0 = 0.0f, u0 = 0.0f;
    bool found = false;

#pragma unroll 1
    for (int k = 0; k < KROUNDS; ++k) {
        uint32_t idx = (uint32_t)k * GAMMA_N + i;
        uint32_t bn = gamma_bits(KEY_N0, KEY_N1, idx);
        uint32_t bu = gamma_bits(KEY_U0, KEY_U1, idx);

        float un = __fadd_rn(__fmul_rn(bits_to_u01(bn), SPAN_N), LO);
        un = fmaxf(LO, un);
        float eps = __fmul_rn(SQRT2, erfinv_xla(un));

        float uu = __fadd_rn(__fmul_rn(bits_to_u01(bu), SPAN_U), UMIN);
        uu = fmaxf(UMIN, uu);

        if (k == 0) { eps0 = eps; u0 = uu; }

        float v = __fadd_rn(1.0f, __fmul_rn(cc, eps));
        bool acc = false;
        if (v > 0.0f) {
            float e2 = __fmul_rn(eps, eps);
            float squeeze = __fadd_rn(1.0f, -__fmul_rn(__fmul_rn(0.0331f, e2), e2));
            if (uu < squeeze) {
                acc = true;
            } else {
                float v3 = __fmul_rn(__fmul_rn(v, v), v);
                float inner = __fadd_rn(__fadd_rn(1.0f, -v3), logf(v3));
                float rhs = __fadd_rn(__fmul_rn(__fmul_rn(0.5f, eps), eps),
                                      __fmul_rn(d, inner));
                if (logf(uu) < rhs) acc = true;
            }
        }
        if (acc) { eps_s = eps; u_s = uu; found = true; break; }
    }
    if (!found) { eps_s = eps0; u_s = u0; }

    float v1 = __fadd_rn(1.0f, __fmul_rn(cc, eps_s));
    float vs = __fmul_rn(v1, __fmul_rn(v1, v1));
    float t1 = logf(__fadd_rn(__fmul_rn(d, vs), 1e-6f));
    float t2 = __fdiv_rn(logf(__fadd_rn(u_s, 1e-6f)), __fadd_rn(al, 1e-6f));
    out_zv = __fdiv_rn(expf(__fadd_rn(t1, t2)), __fadd_rn(be, 1e-6f));
    out_al = al;
    out_be = be;
}

// ---------------------------------------------------------------------------
// mma / ldmatrix / cp.async helpers
// ---------------------------------------------------------------------------
__device__ __forceinline__ uint32_t smem_u32(const void* p) {
    uint32_t a;
    asm("{ .reg .u64 t; cvta.to.shared.u64 t, %1; cvt.u32.u64 %0, t; }"
        : "=r"(a) : "l"(p));
    return a;
}
__device__ __forceinline__ void mma_f16(float* c, const uint32_t* a,
                                        const uint32_t* b) {
    asm volatile(
        "mma.sync.aligned.m16n8k16.row.col.f32.f16.f16.f32 "
        "{%0,%1,%2,%3}, {%4,%5,%6,%7}, {%8,%9}, {%0,%1,%2,%3};"
        : "+f"(c[0]), "+f"(c[1]), "+f"(c[2]), "+f"(c[3])
        : "r"(a[0]), "r"(a[1]), "r"(a[2]), "r"(a[3]),
          "r"(b[0]), "r"(b[1]));
}
__device__ __forceinline__ void ldsm4(uint32_t& r0, uint32_t& r1,
                                      uint32_t& r2, uint32_t& r3, uint32_t a) {
    asm volatile("ldmatrix.sync.aligned.m8n8.x4.shared.b16 {%0,%1,%2,%3}, [%4];"
                 : "=r"(r0), "=r"(r1), "=r"(r2), "=r"(r3) : "r"(a));
}
__device__ __forceinline__ void cpa16(uint32_t dst, const void* src) {
    asm volatile("cp.async.cg.shared.global [%0], [%1], 16;"
                 :: "r"(dst), "l"(src));
}
__device__ __forceinline__ void split_h2(float x, float y,
                                         __half2& hi, __half2& lo) {
    hi = __floats2half2_rn(x, y);
    float2 b = __half22float2(hi);
    lo = __floats2half2_rn(__fadd_rn(x, -b.x), __fadd_rn(y, -b.y));
}
// XOR-swizzled smem byte offset within an 8KB plane
__device__ __forceinline__ uint32_t swz(int row, int q) {
    return (uint32_t)(((row >> 1) << 7) +
                      (((((row & 1) << 2) | q) ^ ((row >> 1) & 7)) << 4));
}

// ---------------------------------------------------------------------------
// GEMM: C[M,N] = act(A[M,K] @ Bt[N,K]^T + bias)
//   CTA 128x128, BK=32, 256 thr, 8 warps (2m x 4n). 3-stage cp.async.
//   NPROD: 3 = ah*bh + ah*bl + al*bh; 1 = ah*bh.
//   ACT: 0 fp32 C; 1 relu half planes (WRLO: also lo); 2 softplus-split;
//        3 fused heads+sampler (C=la, C2=lb, Z=z, Chg=zh).
// ---------------------------------------------------------------------------
#define PLANEB 8192                     // bytes per plane (128 x 64B)
#define STAGEB (4 * PLANEB)             // Ah Al Bh Bl = 32 KB
#define NSTAGE 3

template <int ACT, int NPROD, int WRLO>
__global__ __launch_bounds__(256, 2)
void mma_gemm(const __half* __restrict__ Ahg, const __half* __restrict__ Alg,
              const __half* __restrict__ Bhg, const __half* __restrict__ Blg,
              const float* __restrict__ bias,
              __half* __restrict__ Chg, __half* __restrict__ Clg,
              float* __restrict__ C, float* __restrict__ C2,
              float* __restrict__ Z, int K, int ldc) {
    extern __shared__ __half smh[];
    __shared__ float s_bias[128];

    const int tid  = threadIdx.x;
    const int wid  = tid >> 5;
    const int lane = tid & 31;
    const int qr   = lane >> 2;
    const int qc   = lane & 3;
    const int grp  = lane >> 3;
    const int lr   = lane & 7;
    const int m_w  = (wid >> 2) * 64;
    const int n_w  = (wid & 3) * 32;
    const int row0 = blockIdx.y * 128;
    const int col0 = blockIdx.x * 128;

    if (tid < 128) s_bias[tid] = bias[col0 + tid];

    const uint32_t smb = smem_u32(smh);

    float acc[4][4][4];
#pragma unroll
    for (int a = 0; a < 4; ++a)
#pragma unroll
        for (int b = 0; b < 4; ++b)
#pragma unroll
            for (int c = 0; c < 4; ++c) acc[a][b][c] = 0.0f;

    const int NCH  = K >> 5;
    const int r_ld = tid >> 1;
    const int q0   = (tid & 1) * 2;

    const int growA = row0 + r_ld;
    const int growB = col0 + r_ld;
    const uint32_t d_sw0 = swz(r_ld, q0);
    const uint32_t d_sw1 = swz(r_ld, q0 + 1);

    auto issue = [&](int stage, int kchunk) {
        const int k0 = kchunk << 5;
        const uint32_t sbase = smb + (uint32_t)(stage * STAGEB);
        {
            const __half* s = Ahg + (size_t)growA * K + k0 + q0 * 8;
            cpa16(sbase + d_sw0, s);
            cpa16(sbase + d_sw1, s + 8);
        }
        if (NPROD == 3) {
            const __half* s = Alg + (size_t)growA * K + k0 + q0 * 8;
            cpa16(sbase + (uint32_t)PLANEB + d_sw0, s);
            cpa16(sbase + (uint32_t)PLANEB + d_sw1, s + 8);
        }
        {
            const __half* s = Bhg + (size_t)growB * K + k0 + q0 * 8;
            cpa16(sbase + (uint32_t)(2 * PLANEB) + d_sw0, s);
            cpa16(sbase + (uint32_t)(2 * PLANEB) + d_sw1, s + 8);
        }
        if (NPROD >= 2) {
            const __half* s = Blg + (size_t)growB * K + k0 + q0 * 8;
            cpa16(sbase + (uint32_t)(3 * PLANEB) + d_sw0, s);
            cpa16(sbase + (uint32_t)(3 * PLANEB) + d_sw1, s + 8);
        }
        asm volatile("cp.async.commit_group;" ::: "memory");
    };

    // ---- prolog ----
    issue(0, 0);
    if (NCH > 1) {
        issue(1, 1);
        asm volatile("cp.async.wait_group 1;" ::: "memory");
    } else {
        asm volatile("cp.async.wait_group 0;" ::: "memory");
    }
    __syncthreads();

    for (int i = 0; i < NCH; ++i) {
        if (i + 2 < NCH) issue((i + 2) % NSTAGE, i + 2);

        const uint32_t sb = smb + (uint32_t)((i % NSTAGE) * STAGEB);
#pragma unroll
        for (int ks = 0; ks < 2; ++ks) {
            uint32_t bh[4][2], bl[4][2];
#pragma unroll
            for (int nn = 0; nn < 2; ++nn) {
                const int rB = n_w + nn * 16 + (grp >> 1) * 8 + lr;
                const int qB = ks * 2 + (grp & 1);
                const uint32_t ab = sb + (uint32_t)(2 * PLANEB) + swz(rB, qB);
                ldsm4(bh[2 * nn][0], bh[2 * nn][1],
                      bh[2 * nn + 1][0], bh[2 * nn + 1][1], ab);
                if (NPROD >= 2)
                    ldsm4(bl[2 * nn][0], bl[2 * nn][1],
                          bl[2 * nn + 1][0], bl[2 * nn + 1][1],
                          ab + (uint32_t)PLANEB);
            }
#pragma unroll
            for (int mt = 0; mt < 4; ++mt) {
                uint32_t ah[4], al[4];
                const int rA = m_w + mt * 16 + (grp & 1) * 8 + lr;
                const int qA = ks * 2 + (grp >> 1);
                const uint32_t aa = sb + swz(rA, qA);
                ldsm4(ah[0], ah[1], ah[2], ah[3], aa);
                if (NPROD == 3)
                    ldsm4(al[0], al[1], al[2], al[3], aa + (uint32_t)PLANEB);
#pragma unroll
                for (int nt = 0; nt < 4; ++nt) {
                    mma_f16(acc[mt][nt], ah, bh[nt]);
                    if (NPROD >= 2) mma_f16(acc[mt][nt], ah, bl[nt]);
                    if (NPROD == 3) mma_f16(acc[mt][nt], al, bh[nt]);
                }
            }
        }

        if (i + 1 < NCH) {
            if (i + 2 < NCH) {
                asm volatile("cp.async.wait_group 1;" ::: "memory");
            } else {
                asm volatile("cp.async.wait_group 0;" ::: "memory");
            }
            __syncthreads();
        }
    }

    // ---- epilogue ----
    if (ACT == 3) {
        // fused heads + gamma sampler: stage pre (acc+bias) in smem, pitch 130
        float* sp = reinterpret_cast<float*>(smh);
        __syncthreads();   // mainloop smem reads done before overwrite
#pragma unroll
        for (int mt = 0; mt < 4; ++mt) {
            int rl = m_w + mt * 16 + qr;
#pragma unroll
            for (int nt = 0; nt < 4; ++nt) {
                int lc = n_w + nt * 8 + 2 * qc;
                sp[rl * 130 + lc]           = acc[mt][nt][0] + s_bias[lc];
                sp[rl * 130 + lc + 1]       = acc[mt][nt][1] + s_bias[lc + 1];
                sp[(rl + 8) * 130 + lc]     = acc[mt][nt][2] + s_bias[lc];
                sp[(rl + 8) * 130 + lc + 1] = acc[mt][nt][3] + s_bias[lc + 1];
            }
        }
        __syncthreads();
        const int rloc  = tid >> 1;
        const int lbase = (tid & 1) << 5;
        const int grow  = row0 + rloc;
#pragma unroll 1
        for (int l = 0; l < 32; ++l) {
            int lat = lbase + l;
            uint32_t gi = (uint32_t)grow * 64u + (uint32_t)lat;
            float al, be, zv;
            gamma_one(sp[rloc * 130 + lat], sp[rloc * 130 + 64 + lat],
                      gi, al, be, zv);
            C [gi] = al;
            C2[gi] = be;
            Z [gi] = zv;
            Chg[gi] = __float2half_rn(zv);
        }
        return;
    }

#pragma unroll
    for (int mt = 0; mt < 4; ++mt) {
        int r = row0 + m_w + mt * 16 + qr;
#pragma unroll
        for (int nt = 0; nt < 4; ++nt) {
            int lc = n_w + nt * 8 + 2 * qc;
            int gc = col0 + lc;
            float2 t0, t1;
            t0.x = acc[mt][nt][0] + s_bias[lc];
            t0.y = acc[mt][nt][1] + s_bias[lc + 1];
            t1.x = acc[mt][nt][2] + s_bias[lc];
            t1.y = acc[mt][nt][3] + s_bias[lc + 1];
            if (ACT == 1) {
                t0.x = fmaxf(t0.x, 0.0f); t0.y = fmaxf(t0.y, 0.0f);
                t1.x = fmaxf(t1.x, 0.0f); t1.y = fmaxf(t1.y, 0.0f);
                if (WRLO) {
                    __half2 h2, l2;
                    split_h2(t0.x, t0.y, h2, l2);
                    *reinterpret_cast<__half2*>(&Chg[(size_t)r * ldc + gc]) = h2;
                    *reinterpret_cast<__half2*>(&Clg[(size_t)r * ldc + gc]) = l2;
                    split_h2(t1.x, t1.y, h2, l2);
                    *reinterpret_cast<__half2*>(&Chg[(size_t)(r + 8) * ldc + gc]) = h2;
                    *reinterpret_cast<__half2*>(&Clg[(size_t)(r + 8) * ldc + gc]) = l2;
                } else {
                    *reinterpret_cast<__half2*>(&Chg[(size_t)r * ldc + gc]) =
                        __floats2half2_rn(t0.x, t0.y);
                    *reinterpret_cast<__half2*>(&Chg[(size_t)(r + 8) * ldc + gc]) =
                        __floats2half2_rn(t1.x, t1.y);
                }
            } else if (ACT == 2) {
                t0.x = __fadd_rn(1e-6f, softplusf(t0.x));
                t0.y = __fadd_rn(1e-6f, softplusf(t0.y));
                t1.x = __fadd_rn(1e-6f, softplusf(t1.x));
                t1.y = __fadd_rn(1e-6f, softplusf(t1.y));
                if (gc < 2048) {
                    *reinterpret_cast<float2*>(&C [(size_t)r * 2048 + gc]) = t0;
                    *reinterpret_cast<float2*>(&C [(size_t)(r + 8) * 2048 + gc]) = t1;
                } else {
                    *reinterpret_cast<float2*>(&C2[(size_t)r * 2048 + gc - 2048]) = t0;
                    *reinterpret_cast<float2*>(&C2[(size_t)(r + 8) * 2048 + gc - 2048]) = t1;
                }
            } else {
                *reinterpret_cast<float2*>(&C[(size_t)r * ldc + gc]) = t0;
                *reinterpret_cast<float2*>(&C[(size_t)(r + 8) * ldc + gc]) = t1;
            }
        }
    }
}

// ---------------------------------------------------------------------------
// Batched weight prep (all 9 layers): transpose+split W[K,N] fp32 -> half
// ---------------------------------------------------------------------------
struct WJobs {
    const float* W[9];
    __half* Wh[9];
    __half* Wl[9];
    int K[9], N[9], start[9], wl[9];
    int njobs;
};

__global__ __launch_bounds__(256)
void prep_weights(WJobs j) {
    int b = blockIdx.x;
    int ji = 0;
#pragma unroll
    for (int s = 1; s < 9; ++s)
        if (s < j.njobs && b >= j.start[s]) ji = s;
    const float* W = j.W[ji];
    __half* Wh = j.Wh[ji];
    __half* Wl = j.Wl[ji];
    int K = j.K[ji], N = j.N[ji];
    int wl = j.wl[ji];
    int t = b - j.start[ji];
    int ntn = N >> 5;
    int n0 = (t % ntn) << 5, k0 = (t / ntn) << 5;

    __shared__ float s[32][33];
    int tt = threadIdx.x;
    int a = tt >> 5, bb = tt & 31;
#pragma unroll
    for (int p = 0; p < 4; ++p) {
        int k = p * 8 + a;
        s[k][bb] = W[(size_t)(k0 + k) * N + n0 + bb];
    }
    __syncthreads();
#pragma unroll
    for (int p = 0; p < 4; ++p) {
        int n = p * 8 + a;
        float v = s[bb][n];
        __half h = __float2half_rn(v);
        Wh[(size_t)(n0 + n) * K + k0 + bb] = h;
        if (wl)
            Wl[(size_t)(n0 + n) * K + k0 + bb] =
                __float2half_rn(__fadd_rn(v, -__half2float(h)));
    }
}

// split fp32 activations -> half hi/lo planes; last block concats head bias
__global__ __launch_bounds__(256)
void split_act(const float* __restrict__ X, __half* __restrict__ Xh,
               __half* __restrict__ Xl, int n4,
               const float* __restrict__ hb1, const float* __restrict__ hb2,
               float* __restrict__ bh) {
    if ((int)blockIdx.x == (int)gridDim.x - 1) {
        int t = threadIdx.x;
        if (t < 128) bh[t] = (t < 64) ? hb1[t] : hb2[t - 64];
        return;
    }
    int t = blockIdx.x * blockDim.x + threadIdx.x;
    if (t >= n4) return;
    float4 v = reinterpret_cast<const float4*>(X)[t];
    __half2 h0, l0, h1, l1;
    split_h2(v.x, v.y, h0, l0);
    split_h2(v.z, v.w, h1, l1);
    reinterpret_cast<__half2*>(Xh)[2 * t]     = h0;
    reinterpret_cast<__half2*>(Xh)[2 * t + 1] = h1;
    reinterpret_cast<__half2*>(Xl)[2 * t]     = l0;
    reinterpret_cast<__half2*>(Xl)[2 * t + 1] = l1;
}

// ---------------------------------------------------------------------------
// Launch
// ---------------------------------------------------------------------------
extern "C" void kernel_launch(void* const* d_in, const int* in_sizes, int n_in,
                              void* d_out, int out_size) {
    (void)in_sizes; (void)n_in; (void)out_size;

    const float* x    = (const float*)d_in[0];
    const float* f1w  = (const float*)d_in[1];
    const float* f1b  = (const float*)d_in[2];
    const float* f2w  = (const float*)d_in[3];
    const float* f2b  = (const float*)d_in[4];
    const float* f3w  = (const float*)d_in[5];
    const float* f3b  = (const float*)d_in[6];
    const float* f41w = (const float*)d_in[7];
    const float* f41b = (const float*)d_in[8];
    const float* f42w = (const float*)d_in[9];
    const float* f42b = (const float*)d_in[10];
    const float* f4w  = (const float*)d_in[11];
    const float* f4b  = (const float*)d_in[12];
    const float* f5w  = (const float*)d_in[13];
    const float* f5b  = (const float*)d_in[14];
    const float* f6w  = (const float*)d_in[15];
    const float* f6b  = (const float*)d_in[16];
    const float* f7w  = (const float*)d_in[17];
    const float* f7b  = (const float*)d_in[18];

    float* out = (float*)d_out;
    const size_t OFF_BE = 8192ull * 2048;
    const size_t OFF_LA = 2 * OFF_BE;
    const size_t OFF_LB = OFF_LA + 524288;
    const size_t OFF_Z  = OFF_LB + 524288;

    __half *xh, *xl, *b0h, *b0l, *b1h, *b1l, *zh, *wh, *wl;
    float *bh;
    cudaGetSymbolAddress((void**)&xh,  g_xh);
    cudaGetSymbolAddress((void**)&xl,  g_xl);
    cudaGetSymbolAddress((void**)&b0h, g_b0h);
    cudaGetSymbolAddress((void**)&b0l, g_b0l);
    cudaGetSymbolAddress((void**)&b1h, g_b1h);
    cudaGetSymbolAddress((void**)&b1l, g_b1l);
    cudaGetSymbolAddress((void**)&zh,  g_zh);
    cudaGetSymbolAddress((void**)&wh,  g_wh);
    cudaGetSymbolAddress((void**)&wl,  g_wl);
    cudaGetSymbolAddress((void**)&bh,  g_bh);

    constexpr int DYN = NSTAGE * STAGEB;   // 98304 bytes
    cudaFuncSetAttribute((const void*)mma_gemm<3, 3, 0>, cudaFuncAttributeMaxDynamicSharedMemorySize, DYN);
    cudaFuncSetAttribute((const void*)mma_gemm<1, 3, 1>, cudaFuncAttributeMaxDynamicSharedMemorySize, DYN);
    cudaFuncSetAttribute((const void*)mma_gemm<1, 1, 0>, cudaFuncAttributeMaxDynamicSharedMemorySize, DYN);
    cudaFuncSetAttribute((const void*)mma_gemm<2, 1, 0>, cudaFuncAttributeMaxDynamicSharedMemorySize, DYN);

    // ---- single batched prep (encoder/head weights: hi+lo; decoder: hi) ----
    WJobs jw = {};
    jw.njobs = 9;
    int st = 0;
    auto add = [&](int idx, const float* W, uint32_t off, int K, int N, int wlf) {
        jw.W[idx] = W; jw.Wh[idx] = wh + off; jw.Wl[idx] = wl + off;
        jw.K[idx] = K; jw.N[idx] = N; jw.start[idx] = st; jw.wl[idx] = wlf;
        st += (N >> 5) * (K >> 5);
    };
    add(0, f1w,  OW1, 2048, 1024, 1);
    add(1, f2w,  OW2, 1024, 1024, 1);
    add(2, f3w,  OW3, 1024, 2048, 1);
    add(3, f41w, OWH, 2048, 64,   1);
    add(4, f42w, OWH + 64 * 2048, 2048, 64, 1);
    add(5, f4w,  OW4, 64,   2048, 0);
    add(6, f5w,  OW5, 2048, 1024, 0);
    add(7, f6w,  OW6, 1024, 1024, 0);
    add(8, f7w,  OW7, 1024, 4096, 0);
    prep_weights<<<st, 256>>>(jw);

    split_act<<<(8192 * 2048 / 4) / 256 + 1, 256>>>(x, xh, xl, 8192 * 2048 / 4,
                                                    f41b, f42b, bh);

    // ---- encoder (3-product, exact-class) ----
    mma_gemm<1, 3, 1><<<dim3( 8, 64), 256, DYN>>>(xh,  xl,  wh + OW1, wl + OW1, f1b, b0h, b0l, nullptr, nullptr, nullptr, 2048, 1024);
    mma_gemm<1, 3, 1><<<dim3( 8, 64), 256, DYN>>>(b0h, b0l, wh + OW2, wl + OW2, f2b, b1h, b1l, nullptr, nullptr, nullptr, 1024, 1024);
    mma_gemm<1, 3, 1><<<dim3(16, 64), 256, DYN>>>(b1h, b1l, wh + OW3, wl + OW3, f3b, b0h, b0l, nullptr, nullptr, nullptr, 1024, 2048);
    // fused heads + gamma sampler: outputs la/lb/z + zh for fc4
    mma_gemm<3, 3, 0><<<dim3( 1, 64), 256, DYN>>>(b0h, b0l, wh + OWH, wl + OWH, bh, zh, nullptr,
                                                  out + OFF_LA, out + OFF_LB, out + OFF_Z, 2048, 128);
    // ---- decoder (1-product: fp16 weights x fp16 activations) ----
    mma_gemm<1, 1, 0><<<dim3(16, 64), 256, DYN>>>(zh,  nullptr, wh + OW4, nullptr, f4b, b1h, nullptr, nullptr, nullptr, nullptr, 64, 2048);
    mma_gemm<1, 1, 0><<<dim3( 8, 64), 256, DYN>>>(b1h, nullptr, wh + OW5, nullptr, f5b, b0h, nullptr, nullptr, nullptr, nullptr, 2048, 1024);
    mma_gemm<1, 1, 0><<<dim3( 8, 64), 256, DYN>>>(b0h, nullptr, wh + OW6, nullptr, f6b, b1h, nullptr, nullptr, nullptr, nullptr, 1024, 1024);
    // fc7 with fused softplus-split epilogue -> fp32 outputs
    mma_gemm<2, 1, 0><<<dim3(32, 64), 256, DYN>>>(b1h, nullptr, wh + OW7, nullptr, f7b, nullptr, nullptr, out, out + OFF_BE, nullptr, 1024, 2048);
}

// round 14
// speedup vs baseline: 1.0475x; 1.0475x over previous
#include <cuda_runtime.h>
#include <cuda_fp16.h>
#include <cstdint>
#include <cstddef>

// ============================================================================
// VAE_gamma on GB300. GEMMs: mma.sync m16n8k16.f16 (f32 acc) Markidis split.
// Encoder/heads: 3 products (~fp32 accurate -> sampler decisions exact).
// Decoder: 1 product (fp16 weights x fp16 activations, ~2.2e-4 on recon).
// Heads GEMM split-K=2 (128 CTAs instead of 64). Standalone gamma sampler
// combines partials. Single batched weight prep.
// ============================================================================

#define BATCHN   8192
#define LATENT   64
#define KROUNDS  24
#define GAMMA_N  524288u

// ---------------------------------------------------------------------------
// Scratch (half hi/lo planes)
// ---------------------------------------------------------------------------
__device__ alignas(16) __half g_xh [8192 * 2048];
__device__ alignas(16) __half g_xl [8192 * 2048];
__device__ alignas(16) __half g_b0h[8192 * 2048];
__device__ alignas(16) __half g_b0l[8192 * 2048];
__device__ alignas(16) __half g_b1h[8192 * 2048];
__device__ alignas(16) __half g_b1l[8192 * 2048];
__device__ alignas(16) __half g_zh [8192 * 64];
__device__ alignas(16) __half g_wh [12976128];
__device__ alignas(16) __half g_wl [12976128];
__device__ float g_pre[8192 * 256];     // two K-partials of the heads GEMM
__device__ float g_bh [128];

#define OW1  0u                         // [1024][2048]
#define OW2  (OW1 + 2097152u)           // [1024][1024]
#define OW3  (OW2 + 1048576u)           // [2048][1024]
#define OWH  (OW3 + 2097152u)           // [128][2048]
#define OW4  (OWH + 262144u)            // [2048][64]
#define OW5  (OW4 + 131072u)            // [1024][2048]
#define OW6  (OW5 + 2097152u)           // [1024][1024]
#define OW7  (OW6 + 1048576u)           // [4096][1024]

// ---------------------------------------------------------------------------
// Threefry-2x32 (JAX partitionable mode)
// ---------------------------------------------------------------------------
constexpr unsigned rotlc(unsigned x, int r) { return (x << r) | (x >> (32 - r)); }
constexpr unsigned long long tf_const(unsigned k0, unsigned k1,
                                      unsigned x0, unsigned x1) {
    unsigned kx = k0 ^ k1 ^ 0x1BD11BDAu;
    unsigned ks[3] = {k0, k1, kx};
    const int R0[4] = {13, 15, 26, 6};
    const int R1[4] = {17, 29, 16, 24};
    x0 += k0; x1 += k1;
    for (int i = 0; i < 5; i++) {
        const int* rr = (i % 2 == 0) ? R0 : R1;
        for (int j = 0; j < 4; j++) { x0 += x1; x1 = rotlc(x1, rr[j]); x1 ^= x0; }
        x0 += ks[(i + 1) % 3];
        x1 += ks[(i + 2) % 3] + (unsigned)(i + 1);
    }
    return ((unsigned long long)x0 << 32) | x1;
}
constexpr unsigned long long SPN = tf_const(0u, 42u, 0u, 0u);
constexpr unsigned long long SPU = tf_const(0u, 42u, 0u, 1u);
constexpr unsigned KEY_N0 = (unsigned)(SPN >> 32);
constexpr unsigned KEY_N1 = (unsigned)(SPN & 0xFFFFFFFFu);
constexpr unsigned KEY_U0 = (unsigned)(SPU >> 32);
constexpr unsigned KEY_U1 = (unsigned)(SPU & 0xFFFFFFFFu);

__device__ __forceinline__ uint32_t rotl32(uint32_t x, int r) {
    return __funnelshift_l(x, x, r);
}
__device__ __forceinline__ void tf2x32(uint32_t k0, uint32_t k1,
                                       uint32_t x0, uint32_t x1,
                                       uint32_t& y0, uint32_t& y1) {
    uint32_t kx = k0 ^ k1 ^ 0x1BD11BDAu;
    x0 += k0; x1 += k1;
#define TF_RND(r) { x0 += x1; x1 = rotl32(x1, r); x1 ^= x0; }
    TF_RND(13) TF_RND(15) TF_RND(26) TF_RND(6)   x0 += k1; x1 += kx + 1u;
    TF_RND(17) TF_RND(29) TF_RND(16) TF_RND(24)  x0 += kx; x1 += k0 + 2u;
    TF_RND(13) TF_RND(15) TF_RND(26) TF_RND(6)   x0 += k0; x1 += k1 + 3u;
    TF_RND(17) TF_RND(29) TF_RND(16) TF_RND(24)  x0 += k1; x1 += kx + 4u;
    TF_RND(13) TF_RND(15) TF_RND(26) TF_RND(6)   x0 += kx; x1 += k0 + 5u;
#undef TF_RND
    y0 = x0; y1 = x1;
}
__device__ __forceinline__ uint32_t gamma_bits(uint32_t k0, uint32_t k1,
                                               uint32_t idx) {
    uint32_t y0, y1;
    tf2x32(k0, k1, 0u, idx, y0, y1);
    return y0 ^ y1;
}
__device__ __forceinline__ float bits_to_u01(uint32_t bits) {
    return __uint_as_float((bits >> 9) | 0x3F800000u) - 1.0f;
}
__device__ __forceinline__ float erfinv_xla(float x) {
    float w = -log1pf(-__fmul_rn(x, x));
    float p;
    if (w < 5.0f) {
        w = __fadd_rn(w, -2.5f);
        p = 2.81022636e-08f;
        p = __fadd_rn(__fmul_rn(p, w),  3.43273939e-07f);
        p = __fadd_rn(__fmul_rn(p, w), -3.5233877e-06f);
        p = __fadd_rn(__fmul_rn(p, w), -4.39150654e-06f);
        p = __fadd_rn(__fmul_rn(p, w),  0.00021858087f);
        p = __fadd_rn(__fmul_rn(p, w), -0.00125372503f);
        p = __fadd_rn(__fmul_rn(p, w), -0.00417768164f);
        p = __fadd_rn(__fmul_rn(p, w),  0.246640727f);
        p = __fadd_rn(__fmul_rn(p, w),  1.50140941f);
    } else {
        w = __fadd_rn(__fsqrt_rn(w), -3.0f);
        p = -0.000200214257f;
        p = __fadd_rn(__fmul_rn(p, w),  0.000100950558f);
        p = __fadd_rn(__fmul_rn(p, w),  0.00134934322f);
        p = __fadd_rn(__fmul_rn(p, w), -0.00367342844f);
        p = __fadd_rn(__fmul_rn(p, w),  0.00573950773f);
        p = __fadd_rn(__fmul_rn(p, w), -0.0076224613f);
        p = __fadd_rn(__fmul_rn(p, w),  0.00943887047f);
        p = __fadd_rn(__fmul_rn(p, w),  1.00167406f);
        p = __fadd_rn(__fmul_rn(p, w),  2.83297682f);
    }
    return __fmul_rn(p, x);
}
__device__ __forceinline__ float softplusf(float x) {
    return __fadd_rn(fmaxf(x, 0.0f), log1pf(expf(-fabsf(x))));
}

// ---------------------------------------------------------------------------
// mma / ldmatrix / cp.async helpers
// ---------------------------------------------------------------------------
__device__ __forceinline__ uint32_t smem_u32(const void* p) {
    uint32_t a;
    asm("{ .reg .u64 t; cvta.to.shared.u64 t, %1; cvt.u32.u64 %0, t; }"
        : "=r"(a) : "l"(p));
    return a;
}
__device__ __forceinline__ void mma_f16(float* c, const uint32_t* a,
                                        const uint32_t* b) {
    asm volatile(
        "mma.sync.aligned.m16n8k16.row.col.f32.f16.f16.f32 "
        "{%0,%1,%2,%3}, {%4,%5,%6,%7}, {%8,%9}, {%0,%1,%2,%3};"
        : "+f"(c[0]), "+f"(c[1]), "+f"(c[2]), "+f"(c[3])
        : "r"(a[0]), "r"(a[1]), "r"(a[2]), "r"(a[3]),
          "r"(b[0]), "r"(b[1]));
}
__device__ __forceinline__ void ldsm4(uint32_t& r0, uint32_t& r1,
                                      uint32_t& r2, uint32_t& r3, uint32_t a) {
    asm volatile("ldmatrix.sync.aligned.m8n8.x4.shared.b16 {%0,%1,%2,%3}, [%4];"
                 : "=r"(r0), "=r"(r1), "=r"(r2), "=r"(r3) : "r"(a));
}
__device__ __forceinline__ void cpa16(uint32_t dst, const void* src) {
    asm volatile("cp.async.cg.shared.global [%0], [%1], 16;"
                 :: "r"(dst), "l"(src));
}
__device__ __forceinline__ void split_h2(float x, float y,
                                         __half2& hi, __half2& lo) {
    hi = __floats2half2_rn(x, y);
    float2 b = __half22float2(hi);
    lo = __floats2half2_rn(__fadd_rn(x, -b.x), __fadd_rn(y, -b.y));
}
// XOR-swizzled smem byte offset within an 8KB plane
__device__ __forceinline__ uint32_t swz(int row, int q) {
    return (uint32_t)(((row >> 1) << 7) +
                      (((((row & 1) << 2) | q) ^ ((row >> 1) & 7)) << 4));
}

// ---------------------------------------------------------------------------
// GEMM: C[M,N] = act(A[M,K] @ Bt[N,K]^T + bias)
//   CTA 128x128, BK=32, 256 thr, 8 warps (2m x 4n). 3-stage cp.async.
//   NPROD: 3 = ah*bh + ah*bl + al*bh; 1 = ah*bh.
//   ACT: 0 fp32 partial (no bias if SPLITK; +z-offset); 1 relu half planes
//        (WRLO: also lo); 2 softplus-split.
//   SPLITK: blockIdx.z selects K-window [z*K, (z+1)*K); lda = full row stride.
// ---------------------------------------------------------------------------
#define PLANEB 8192                     // bytes per plane (128 x 64B)
#define STAGEB (4 * PLANEB)             // Ah Al Bh Bl = 32 KB
#define NSTAGE 3

template <int ACT, int NPROD, int WRLO, int SPLITK>
__global__ __launch_bounds__(256, 2)
void mma_gemm(const __half* __restrict__ Ahg, const __half* __restrict__ Alg,
              const __half* __restrict__ Bhg, const __half* __restrict__ Blg,
              const float* __restrict__ bias,
              __half* __restrict__ Chg, __half* __restrict__ Clg,
              float* __restrict__ C, float* __restrict__ C2,
              int K, int lda, int ldc) {
    extern __shared__ __half smh[];
    __shared__ float s_bias[128];

    const int tid  = threadIdx.x;
    const int wid  = tid >> 5;
    const int lane = tid & 31;
    const int qr   = lane >> 2;
    const int qc   = lane & 3;
    const int grp  = lane >> 3;
    const int lr   = lane & 7;
    const int m_w  = (wid >> 2) * 64;
    const int n_w  = (wid & 3) * 32;
    const int row0 = blockIdx.y * 128;
    const int col0 = blockIdx.x * 128;
    const int kb   = SPLITK ? ((int)blockIdx.z * K) : 0;

    if (tid < 128) s_bias[tid] = bias[col0 + tid];

    const uint32_t smb = smem_u32(smh);

    float acc[4][4][4];
#pragma unroll
    for (int a = 0; a < 4; ++a)
#pragma unroll
        for (int b = 0; b < 4; ++b)
#pragma unroll
            for (int c = 0; c < 4; ++c) acc[a][b][c] = 0.0f;

    const int NCH  = K >> 5;
    const int r_ld = tid >> 1;
    const int q0   = (tid & 1) * 2;

    const int growA = row0 + r_ld;
    const int growB = col0 + r_ld;
    const uint32_t d_sw0 = swz(r_ld, q0);
    const uint32_t d_sw1 = swz(r_ld, q0 + 1);

    auto issue = [&](int stage, int kchunk) {
        const int k0 = kb + (kchunk << 5);
        const uint32_t sbase = smb + (uint32_t)(stage * STAGEB);
        {
            const __half* s = Ahg + (size_t)growA * lda + k0 + q0 * 8;
            cpa16(sbase + d_sw0, s);
            cpa16(sbase + d_sw1, s + 8);
        }
        if (NPROD == 3) {
            const __half* s = Alg + (size_t)growA * lda + k0 + q0 * 8;
            cpa16(sbase + (uint32_t)PLANEB + d_sw0, s);
            cpa16(sbase + (uint32_t)PLANEB + d_sw1, s + 8);
        }
        {
            const __half* s = Bhg + (size_t)growB * lda + k0 + q0 * 8;
            cpa16(sbase + (uint32_t)(2 * PLANEB) + d_sw0, s);
            cpa16(sbase + (uint32_t)(2 * PLANEB) + d_sw1, s + 8);
        }
        if (NPROD >= 2) {
            const __half* s = Blg + (size_t)growB * lda + k0 + q0 * 8;
            cpa16(sbase + (uint32_t)(3 * PLANEB) + d_sw0, s);
            cpa16(sbase + (uint32_t)(3 * PLANEB) + d_sw1, s + 8);
        }
        asm volatile("cp.async.commit_group;" ::: "memory");
    };

    // ---- prolog ----
    issue(0, 0);
    if (NCH > 1) {
        issue(1, 1);
        asm volatile("cp.async.wait_group 1;" ::: "memory");
    } else {
        asm volatile("cp.async.wait_group 0;" ::: "memory");
    }
    __syncthreads();

    for (int i = 0; i < NCH; ++i) {
        if (i + 2 < NCH) issue((i + 2) % NSTAGE, i + 2);

        const uint32_t sb = smb + (uint32_t)((i % NSTAGE) * STAGEB);
#pragma unroll
        for (int ks = 0; ks < 2; ++ks) {
            uint32_t bh[4][2], bl[4][2];
#pragma unroll
            for (int nn = 0; nn < 2; ++nn) {
                const int rB = n_w + nn * 16 + (grp >> 1) * 8 + lr;
                const int qB = ks * 2 + (grp & 1);
                const uint32_t ab = sb + (uint32_t)(2 * PLANEB) + swz(rB, qB);
                ldsm4(bh[2 * nn][0], bh[2 * nn][1],
                      bh[2 * nn + 1][0], bh[2 * nn + 1][1], ab);
                if (NPROD >= 2)
                    ldsm4(bl[2 * nn][0], bl[2 * nn][1],
                          bl[2 * nn + 1][0], bl[2 * nn + 1][1],
                          ab + (uint32_t)PLANEB);
            }
#pragma unroll
            for (int mt = 0; mt < 4; ++mt) {
                uint32_t ah[4], al[4];
                const int rA = m_w + mt * 16 + (grp & 1) * 8 + lr;
                const int qA = ks * 2 + (grp >> 1);
                const uint32_t aa = sb + swz(rA, qA);
                ldsm4(ah[0], ah[1], ah[2], ah[3], aa);
                if (NPROD == 3)
                    ldsm4(al[0], al[1], al[2], al[3], aa + (uint32_t)PLANEB);
#pragma unroll
                for (int nt = 0; nt < 4; ++nt) {
                    mma_f16(acc[mt][nt], ah, bh[nt]);
                    if (NPROD >= 2) mma_f16(acc[mt][nt], ah, bl[nt]);
                    if (NPROD == 3) mma_f16(acc[mt][nt], al, bh[nt]);
                }
            }
        }

        if (i + 1 < NCH) {
            if (i + 2 < NCH) {
                asm volatile("cp.async.wait_group 1;" ::: "memory");
            } else {
                asm volatile("cp.async.wait_group 0;" ::: "memory");
            }
            __syncthreads();
        }
    }

    // ---- epilogue ----
    float* Cz = SPLITK ? (C + (size_t)blockIdx.z * (8192ull * 128)) : C;
#pragma unroll
    for (int mt = 0; mt < 4; ++mt) {
        int r = row0 + m_w + mt * 16 + qr;
#pragma unroll
        for (int nt = 0; nt < 4; ++nt) {
            int lc = n_w + nt * 8 + 2 * qc;
            int gc = col0 + lc;
            float2 t0, t1;
            float b0v = SPLITK ? 0.0f : s_bias[lc];
            float b1v = SPLITK ? 0.0f : s_bias[lc + 1];
            t0.x = acc[mt][nt][0] + b0v;
            t0.y = acc[mt][nt][1] + b1v;
            t1.x = acc[mt][nt][2] + b0v;
            t1.y = acc[mt][nt][3] + b1v;
            if (ACT == 1) {
                t0.x = fmaxf(t0.x, 0.0f); t0.y = fmaxf(t0.y, 0.0f);
                t1.x = fmaxf(t1.x, 0.0f); t1.y = fmaxf(t1.y, 0.0f);
                if (WRLO) {
                    __half2 h2, l2;
                    split_h2(t0.x, t0.y, h2, l2);
                    *reinterpret_cast<__half2*>(&Chg[(size_t)r * ldc + gc]) = h2;
                    *reinterpret_cast<__half2*>(&Clg[(size_t)r * ldc + gc]) = l2;
                    split_h2(t1.x, t1.y, h2, l2);
                    *reinterpret_cast<__half2*>(&Chg[(size_t)(r + 8) * ldc + gc]) = h2;
                    *reinterpret_cast<__half2*>(&Clg[(size_t)(r + 8) * ldc + gc]) = l2;
                } else {
                    *reinterpret_cast<__half2*>(&Chg[(size_t)r * ldc + gc]) =
                        __floats2half2_rn(t0.x, t0.y);
                    *reinterpret_cast<__half2*>(&Chg[(size_t)(r + 8) * ldc + gc]) =
                        __floats2half2_rn(t1.x, t1.y);
                }
            } else if (ACT == 2) {
                t0.x = __fadd_rn(1e-6f, softplusf(t0.x));
                t0.y = __fadd_rn(1e-6f, softplusf(t0.y));
                t1.x = __fadd_rn(1e-6f, softplusf(t1.x));
                t1.y = __fadd_rn(1e-6f, softplusf(t1.y));
                if (gc < 2048) {
                    *reinterpret_cast<float2*>(&C [(size_t)r * 2048 + gc]) = t0;
                    *reinterpret_cast<float2*>(&C [(size_t)(r + 8) * 2048 + gc]) = t1;
                } else {
                    *reinterpret_cast<float2*>(&C2[(size_t)r * 2048 + gc - 2048]) = t0;
                    *reinterpret_cast<float2*>(&C2[(size_t)(r + 8) * 2048 + gc - 2048]) = t1;
                }
            } else {
                *reinterpret_cast<float2*>(&Cz[(size_t)r * ldc + gc]) = t0;
                *reinterpret_cast<float2*>(&Cz[(size_t)(r + 8) * ldc + gc]) = t1;
            }
        }
    }
}

// ---------------------------------------------------------------------------
// Batched weight prep (all 9 layers): transpose+split W[K,N] fp32 -> half
// ---------------------------------------------------------------------------
struct WJobs {
    const float* W[9];
    __half* Wh[9];
    __half* Wl[9];
    int K[9], N[9], start[9], wl[9];
    int njobs;
};

__global__ __launch_bounds__(256)
void prep_weights(WJobs j) {
    int b = blockIdx.x;
    int ji = 0;
#pragma unroll
    for (int s = 1; s < 9; ++s)
        if (s < j.njobs && b >= j.start[s]) ji = s;
    const float* W = j.W[ji];
    __half* Wh = j.Wh[ji];
    __half* Wl = j.Wl[ji];
    int K = j.K[ji], N = j.N[ji];
    int wl = j.wl[ji];
    int t = b - j.start[ji];
    int ntn = N >> 5;
    int n0 = (t % ntn) << 5, k0 = (t / ntn) << 5;

    __shared__ float s[32][33];
    int tt = threadIdx.x;
    int a = tt >> 5, bb = tt & 31;
#pragma unroll
    for (int p = 0; p < 4; ++p) {
        int k = p * 8 + a;
        s[k][bb] = W[(size_t)(k0 + k) * N + n0 + bb];
    }
    __syncthreads();
#pragma unroll
    for (int p = 0; p < 4; ++p) {
        int n = p * 8 + a;
        float v = s[bb][n];
        __half h = __float2half_rn(v);
        Wh[(size_t)(n0 + n) * K + k0 + bb] = h;
        if (wl)
            Wl[(size_t)(n0 + n) * K + k0 + bb] =
                __float2half_rn(__fadd_rn(v, -__half2float(h)));
    }
}

// split fp32 activations -> half hi/lo planes; last block concats head bias
__global__ __launch_bounds__(256)
void split_act(const float* __restrict__ X, __half* __restrict__ Xh,
               __half* __restrict__ Xl, int n4,
               const float* __restrict__ hb1, const float* __restrict__ hb2,
               float* __restrict__ bh) {
    if ((int)blockIdx.x == (int)gridDim.x - 1) {
        int t = threadIdx.x;
        if (t < 128) bh[t] = (t < 64) ? hb1[t] : hb2[t - 64];
        return;
    }
    int t = blockIdx.x * blockDim.x + threadIdx.x;
    if (t >= n4) return;
    float4 v = reinterpret_cast<const float4*>(X)[t];
    __half2 h0, l0, h1, l1;
    split_h2(v.x, v.y, h0, l0);
    split_h2(v.z, v.w, h1, l1);
    reinterpret_cast<__half2*>(Xh)[2 * t]     = h0;
    reinterpret_cast<__half2*>(Xh)[2 * t + 1] = h1;
    reinterpret_cast<__half2*>(Xl)[2 * t]     = l0;
    reinterpret_cast<__half2*>(Xl)[2 * t + 1] = l1;
}

// ---------------------------------------------------------------------------
// Gamma sampler: combines two K-partials + bias, then samples.
// ---------------------------------------------------------------------------
__global__ __launch_bounds__(256)
void gamma_sampler(const float* __restrict__ pre, const float* __restrict__ bh,
                   float* __restrict__ out_la, float* __restrict__ out_lb,
                   float* __restrict__ out_z, __half* __restrict__ zh) {
    int i = blockIdx.x * blockDim.x + threadIdx.x;
    if (i >= BATCHN * LATENT) return;
    int row = i >> 6, lat = i & 63;

    const float* p1 = pre + 8192ull * 128;
    float preA = (pre[row * 128 + lat]      + p1[row * 128 + lat])      + bh[lat];
    float preB = (pre[row * 128 + 64 + lat] + p1[row * 128 + 64 + lat]) + bh[64 + lat];

    float al = __fadd_rn(1e-6f, softplusf(preA));
    float be = __fadd_rn(1e-6f, softplusf(preB));

    float d  = __fadd_rn(__fadd_rn(al, 1.0f), -(1.0f / 3.0f));
    float cc = __fdiv_rn(1.0f, __fsqrt_rn(__fmul_rn(9.0f, d)));

    const float LO     = -0.99999994f;
    const float SPAN_N = 2.0f;
    const float UMIN   = 1e-7f;
    const float SPAN_U = 1.0f - 1e-7f;
    const float SQRT2  = 1.41421356f;

    float eps_s = 0.0f, u_s = 0.0f, eps0 = 0.0f, u0 = 0.0f;
    bool found = false;

#pragma unroll 1
    for (int k = 0; k < KROUNDS; ++k) {
        uint32_t idx = (uint32_t)k * GAMMA_N + (uint32_t)i;
        uint32_t bn = gamma_bits(KEY_N0, KEY_N1, idx);
        uint32_t bu = gamma_bits(KEY_U0, KEY_U1, idx);

        float un = __fadd_rn(__fmul_rn(bits_to_u01(bn), SPAN_N), LO);
        un = fmaxf(LO, un);
        float eps = __fmul_rn(SQRT2, erfinv_xla(un));

        float uu = __fadd_rn(__fmul_rn(bits_to_u01(bu), SPAN_U), UMIN);
        uu = fmaxf(UMIN, uu);

        if (k == 0) { eps0 = eps; u0 = uu; }

        float v = __fadd_rn(1.0f, __fmul_rn(cc, eps));
        bool acc = false;
        if (v > 0.0f) {
            float e2 = __fmul_rn(eps, eps);
            float squeeze = __fadd_rn(1.0f, -__fmul_rn(__fmul_rn(0.0331f, e2), e2));
            if (uu < squeeze) {
                acc = true;
            } else {
                float v3 = __fmul_rn(__fmul_rn(v, v), v);
                float inner = __fadd_rn(__fadd_rn(1.0f, -v3), logf(v3));
                float rhs = __fadd_rn(__fmul_rn(__fmul_rn(0.5f, eps), eps),
                                      __fmul_rn(d, inner));
                if (logf(uu) < rhs) acc = true;
            }
        }
        if (acc) { eps_s = eps; u_s = uu; found = true; break; }
    }
    if (!found) { eps_s = eps0; u_s = u0; }

    float v1 = __fadd_rn(1.0f, __fmul_rn(cc, eps_s));
    float vs = __fmul_rn(v1, __fmul_rn(v1, v1));
    float t1 = logf(__fadd_rn(__fmul_rn(d, vs), 1e-6f));
    float t2 = __fdiv_rn(logf(__fadd_rn(u_s, 1e-6f)), __fadd_rn(al, 1e-6f));
    float z  = __fdiv_rn(expf(__fadd_rn(t1, t2)), __fadd_rn(be, 1e-6f));

    out_la[i] = al;
    out_lb[i] = be;
    out_z[i]  = z;
    zh[i] = __float2half_rn(z);
}

// ---------------------------------------------------------------------------
// Launch
// ---------------------------------------------------------------------------
extern "C" void kernel_launch(void* const* d_in, const int* in_sizes, int n_in,
                              void* d_out, int out_size) {
    (void)in_sizes; (void)n_in; (void)out_size;

    const float* x    = (const float*)d_in[0];
    const float* f1w  = (const float*)d_in[1];
    const float* f1b  = (const float*)d_in[2];
    const float* f2w  = (const float*)d_in[3];
    const float* f2b  = (const float*)d_in[4];
    const float* f3w  = (const float*)d_in[5];
    const float* f3b  = (const float*)d_in[6];
    const float* f41w = (const float*)d_in[7];
    const float* f41b = (const float*)d_in[8];
    const float* f42w = (const float*)d_in[9];
    const float* f42b = (const float*)d_in[10];
    const float* f4w  = (const float*)d_in[11];
    const float* f4b  = (const float*)d_in[12];
    const float* f5w  = (const float*)d_in[13];
    const float* f5b  = (const float*)d_in[14];
    const float* f6w  = (const float*)d_in[15];
    const float* f6b  = (const float*)d_in[16];
    const float* f7w  = (const float*)d_in[17];
    const float* f7b  = (const float*)d_in[18];

    float* out = (float*)d_out;
    const size_t OFF_BE = 8192ull * 2048;
    const size_t OFF_LA = 2 * OFF_BE;
    const size_t OFF_LB = OFF_LA + 524288;
    const size_t OFF_Z  = OFF_LB + 524288;

    __half *xh, *xl, *b0h, *b0l, *b1h, *b1l, *zh, *wh, *wl;
    float *pre, *bh;
    cudaGetSymbolAddress((void**)&xh,  g_xh);
    cudaGetSymbolAddress((void**)&xl,  g_xl);
    cudaGetSymbolAddress((void**)&b0h, g_b0h);
    cudaGetSymbolAddress((void**)&b0l, g_b0l);
    cudaGetSymbolAddress((void**)&b1h, g_b1h);
    cudaGetSymbolAddress((void**)&b1l, g_b1l);
    cudaGetSymbolAddress((void**)&zh,  g_zh);
    cudaGetSymbolAddress((void**)&wh,  g_wh);
    cudaGetSymbolAddress((void**)&wl,  g_wl);
    cudaGetSymbolAddress((void**)&pre, g_pre);
    cudaGetSymbolAddress((void**)&bh,  g_bh);

    constexpr int DYN = NSTAGE * STAGEB;   // 98304 bytes
    cudaFuncSetAttribute((const void*)mma_gemm<0, 3, 0, 1>, cudaFuncAttributeMaxDynamicSharedMemorySize, DYN);
    cudaFuncSetAttribute((const void*)mma_gemm<1, 3, 1, 0>, cudaFuncAttributeMaxDynamicSharedMemorySize, DYN);
    cudaFuncSetAttribute((const void*)mma_gemm<1, 1, 0, 0>, cudaFuncAttributeMaxDynamicSharedMemorySize, DYN);
    cudaFuncSetAttribute((const void*)mma_gemm<2, 1, 0, 0>, cudaFuncAttributeMaxDynamicSharedMemorySize, DYN);

    // ---- single batched prep (encoder/head weights: hi+lo; decoder: hi) ----
    WJobs jw = {};
    jw.njobs = 9;
    int st = 0;
    auto add = [&](int idx, const float* W, uint32_t off, int K, int N, int wlf) {
        jw.W[idx] = W; jw.Wh[idx] = wh + off; jw.Wl[idx] = wl + off;
        jw.K[idx] = K; jw.N[idx] = N; jw.start[idx] = st; jw.wl[idx] = wlf;
        st += (N >> 5) * (K >> 5);
    };
    add(0, f1w,  OW1, 2048, 1024, 1);
    add(1, f2w,  OW2, 1024, 1024, 1);
    add(2, f3w,  OW3, 1024, 2048, 1);
    add(3, f41w, OWH, 2048, 64,   1);
    add(4, f42w, OWH + 64 * 2048, 2048, 64, 1);
    add(5, f4w,  OW4, 64,   2048, 0);
    add(6, f5w,  OW5, 2048, 1024, 0);
    add(7, f6w,  OW6, 1024, 1024, 0);
    add(8, f7w,  OW7, 1024, 4096, 0);
    prep_weights<<<st, 256>>>(jw);

    split_act<<<(8192 * 2048 / 4) / 256 + 1, 256>>>(x, xh, xl, 8192 * 2048 / 4,
                                                    f41b, f42b, bh);

    // ---- encoder (3-product, exact-class) ----
    mma_gemm<1, 3, 1, 0><<<dim3( 8, 64), 256, DYN>>>(xh,  xl,  wh + OW1, wl + OW1, f1b, b0h, b0l, nullptr, nullptr, 2048, 2048, 1024);
    mma_gemm<1, 3, 1, 0><<<dim3( 8, 64), 256, DYN>>>(b0h, b0l, wh + OW2, wl + OW2, f2b, b1h, b1l, nullptr, nullptr, 1024, 1024, 1024);
    mma_gemm<1, 3, 1, 0><<<dim3(16, 64), 256, DYN>>>(b1h, b1l, wh + OW3, wl + OW3, f3b, b0h, b0l, nullptr, nullptr, 1024, 1024, 2048);
    // fused heads, split-K=2: partials (no bias) -> pre[0], pre[1M]
    mma_gemm<0, 3, 0, 1><<<dim3(1, 64, 2), 256, DYN>>>(b0h, b0l, wh + OWH, wl + OWH, bh, nullptr, nullptr, pre, nullptr, 1024, 2048, 128);
    // ---- gamma reparameterization (combines partials + bias) ----
    gamma_sampler<<<(BATCHN * LATENT) / 256, 256>>>(
        pre, bh, out + OFF_LA, out + OFF_LB, out + OFF_Z, zh);
    // ---- decoder (1-product: fp16 weights x fp16 activations) ----
    mma_gemm<1, 1, 0, 0><<<dim3(16, 64), 256, DYN>>>(zh,  nullptr, wh + OW4, nullptr, f4b, b1h, nullptr, nullptr, nullptr, 64, 64, 2048);
    mma_gemm<1, 1, 0, 0><<<dim3( 8, 64), 256, DYN>>>(b1h, nullptr, wh + OW5, nullptr, f5b, b0h, nullptr, nullptr, nullptr, 2048, 2048, 1024);
    mma_gemm<1, 1, 0, 0><<<dim3( 8, 64), 256, DYN>>>(b0h, nullptr, wh + OW6, nullptr, f6b, b1h, nullptr, nullptr, nullptr, 1024, 1024, 1024);
    // fc7 with fused softplus-split epilogue -> fp32 outputs
    mma_gemm<2, 1, 0, 0><<<dim3(32, 64), 256, DYN>>>(b1h, nullptr, wh + OW7, nullptr, f7b, nullptr, nullptr, out, out + OFF_BE, 1024, 1024, 2048);
}

// round 15
// speedup vs baseline: 1.0479x; 1.0004x over previous
#include <cuda_runtime.h>
#include <cuda_fp16.h>
#include <cstdint>
#include <cstddef>

// ============================================================================
// VAE_gamma on GB300. GEMMs: mma.sync m16n8k16.f16 (f32 acc) Markidis split.
// Encoder/heads: 3 products (~fp32 accurate -> sampler decisions exact).
// Decoder: 1 product (fp16 weights x fp16 activations, ~2.2e-4 on recon).
// Heads GEMM split-K=2. Standalone gamma sampler combines partials.
// ONE merged prep launch: 9 weight transpose/split jobs + x-split + bias.
// ============================================================================

#define BATCHN   8192
#define LATENT   64
#define KROUNDS  24
#define GAMMA_N  524288u

// ---------------------------------------------------------------------------
// Scratch (half hi/lo planes)
// ---------------------------------------------------------------------------
__device__ alignas(16) __half g_xh [8192 * 2048];
__device__ alignas(16) __half g_xl [8192 * 2048];
__device__ alignas(16) __half g_b0h[8192 * 2048];
__device__ alignas(16) __half g_b0l[8192 * 2048];
__device__ alignas(16) __half g_b1h[8192 * 2048];
__device__ alignas(16) __half g_b1l[8192 * 2048];
__device__ alignas(16) __half g_zh [8192 * 64];
__device__ alignas(16) __half g_wh [12976128];
__device__ alignas(16) __half g_wl [12976128];
__device__ float g_pre[8192 * 256];     // two K-partials of the heads GEMM
__device__ float g_bh [128];

#define OW1  0u                         // [1024][2048]
#define OW2  (OW1 + 2097152u)           // [1024][1024]
#define OW3  (OW2 + 1048576u)           // [2048][1024]
#define OWH  (OW3 + 2097152u)           // [128][2048]
#define OW4  (OWH + 262144u)            // [2048][64]
#define OW5  (OW4 + 131072u)            // [1024][2048]
#define OW6  (OW5 + 2097152u)           // [1024][1024]
#define OW7  (OW6 + 1048576u)           // [4096][1024]

// ---------------------------------------------------------------------------
// Threefry-2x32 (JAX partitionable mode)
// ---------------------------------------------------------------------------
constexpr unsigned rotlc(unsigned x, int r) { return (x << r) | (x >> (32 - r)); }
constexpr unsigned long long tf_const(unsigned k0, unsigned k1,
                                      unsigned x0, unsigned x1) {
    unsigned kx = k0 ^ k1 ^ 0x1BD11BDAu;
    unsigned ks[3] = {k0, k1, kx};
    const int R0[4] = {13, 15, 26, 6};
    const int R1[4] = {17, 29, 16, 24};
    x0 += k0; x1 += k1;
    for (int i = 0; i < 5; i++) {
        const int* rr = (i % 2 == 0) ? R0 : R1;
        for (int j = 0; j < 4; j++) { x0 += x1; x1 = rotlc(x1, rr[j]); x1 ^= x0; }
        x0 += ks[(i + 1) % 3];
        x1 += ks[(i + 2) % 3] + (unsigned)(i + 1);
    }
    return ((unsigned long long)x0 << 32) | x1;
}
constexpr unsigned long long SPN = tf_const(0u, 42u, 0u, 0u);
constexpr unsigned long long SPU = tf_const(0u, 42u, 0u, 1u);
constexpr unsigned KEY_N0 = (unsigned)(SPN >> 32);
constexpr unsigned KEY_N1 = (unsigned)(SPN & 0xFFFFFFFFu);
constexpr unsigned KEY_U0 = (unsigned)(SPU >> 32);
constexpr unsigned KEY_U1 = (unsigned)(SPU & 0xFFFFFFFFu);

__device__ __forceinline__ uint32_t rotl32(uint32_t x, int r) {
    return __funnelshift_l(x, x, r);
}
__device__ __forceinline__ void tf2x32(uint32_t k0, uint32_t k1,
                                       uint32_t x0, uint32_t x1,
                                       uint32_t& y0, uint32_t& y1) {
    uint32_t kx = k0 ^ k1 ^ 0x1BD11BDAu;
    x0 += k0; x1 += k1;
#define TF_RND(r) { x0 += x1; x1 = rotl32(x1, r); x1 ^= x0; }
    TF_RND(13) TF_RND(15) TF_RND(26) TF_RND(6)   x0 += k1; x1 += kx + 1u;
    TF_RND(17) TF_RND(29) TF_RND(16) TF_RND(24)  x0 += kx; x1 += k0 + 2u;
    TF_RND(13) TF_RND(15) TF_RND(26) TF_RND(6)   x0 += k0; x1 += k1 + 3u;
    TF_RND(17) TF_RND(29) TF_RND(16) TF_RND(24)  x0 += k1; x1 += kx + 4u;
    TF_RND(13) TF_RND(15) TF_RND(26) TF_RND(6)   x0 += kx; x1 += k0 + 5u;
#undef TF_RND
    y0 = x0; y1 = x1;
}
__device__ __forceinline__ uint32_t gamma_bits(uint32_t k0, uint32_t k1,
                                               uint32_t idx) {
    uint32_t y0, y1;
    tf2x32(k0, k1, 0u, idx, y0, y1);
    return y0 ^ y1;
}
__device__ __forceinline__ float bits_to_u01(uint32_t bits) {
    return __uint_as_float((bits >> 9) | 0x3F800000u) - 1.0f;
}
__device__ __forceinline__ float erfinv_xla(float x) {
    float w = -log1pf(-__fmul_rn(x, x));
    float p;
    if (w < 5.0f) {
        w = __fadd_rn(w, -2.5f);
        p = 2.81022636e-08f;
        p = __fadd_rn(__fmul_rn(p, w),  3.43273939e-07f);
        p = __fadd_rn(__fmul_rn(p, w), -3.5233877e-06f);
        p = __fadd_rn(__fmul_rn(p, w), -4.39150654e-06f);
        p = __fadd_rn(__fmul_rn(p, w),  0.00021858087f);
        p = __fadd_rn(__fmul_rn(p, w), -0.00125372503f);
        p = __fadd_rn(__fmul_rn(p, w), -0.00417768164f);
        p = __fadd_rn(__fmul_rn(p, w),  0.246640727f);
        p = __fadd_rn(__fmul_rn(p, w),  1.50140941f);
    } else {
        w = __fadd_rn(__fsqrt_rn(w), -3.0f);
        p = -0.000200214257f;
        p = __fadd_rn(__fmul_rn(p, w),  0.000100950558f);
        p = __fadd_rn(__fmul_rn(p, w),  0.00134934322f);
        p = __fadd_rn(__fmul_rn(p, w), -0.00367342844f);
        p = __fadd_rn(__fmul_rn(p, w),  0.00573950773f);
        p = __fadd_rn(__fmul_rn(p, w), -0.0076224613f);
        p = __fadd_rn(__fmul_rn(p, w),  0.00943887047f);
        p = __fadd_rn(__fmul_rn(p, w),  1.00167406f);
        p = __fadd_rn(__fmul_rn(p, w),  2.83297682f);
    }
    return __fmul_rn(p, x);
}
__device__ __forceinline__ float softplusf(float x) {
    return __fadd_rn(fmaxf(x, 0.0f), log1pf(expf(-fabsf(x))));
}

// ---------------------------------------------------------------------------
// mma / ldmatrix / cp.async helpers
// ---------------------------------------------------------------------------
__device__ __forceinline__ uint32_t smem_u32(const void* p) {
    uint32_t a;
    asm("{ .reg .u64 t; cvta.to.shared.u64 t, %1; cvt.u32.u64 %0, t; }"
        : "=r"(a) : "l"(p));
    return a;
}
__device__ __forceinline__ void mma_f16(float* c, const uint32_t* a,
                                        const uint32_t* b) {
    asm volatile(
        "mma.sync.aligned.m16n8k16.row.col.f32.f16.f16.f32 "
        "{%0,%1,%2,%3}, {%4,%5,%6,%7}, {%8,%9}, {%0,%1,%2,%3};"
        : "+f"(c[0]), "+f"(c[1]), "+f"(c[2]), "+f"(c[3])
        : "r"(a[0]), "r"(a[1]), "r"(a[2]), "r"(a[3]),
          "r"(b[0]), "r"(b[1]));
}
__device__ __forceinline__ void ldsm4(uint32_t& r0, uint32_t& r1,
                                      uint32_t& r2, uint32_t& r3, uint32_t a) {
    asm volatile("ldmatrix.sync.aligned.m8n8.x4.shared.b16 {%0,%1,%2,%3}, [%4];"
                 : "=r"(r0), "=r"(r1), "=r"(r2), "=r"(r3) : "r"(a));
}
__device__ __forceinline__ void cpa16(uint32_t dst, const void* src) {
    asm volatile("cp.async.cg.shared.global [%0], [%1], 16;"
                 :: "r"(dst), "l"(src));
}
__device__ __forceinline__ void split_h2(float x, float y,
                                         __half2& hi, __half2& lo) {
    hi = __floats2half2_rn(x, y);
    float2 b = __half22float2(hi);
    lo = __floats2half2_rn(__fadd_rn(x, -b.x), __fadd_rn(y, -b.y));
}
// XOR-swizzled smem byte offset within an 8KB plane
__device__ __forceinline__ uint32_t swz(int row, int q) {
    return (uint32_t)(((row >> 1) << 7) +
                      (((((row & 1) << 2) | q) ^ ((row >> 1) & 7)) << 4));
}

// ---------------------------------------------------------------------------
// GEMM: C[M,N] = act(A[M,K] @ Bt[N,K]^T + bias)
//   CTA 128x128, BK=32, 256 thr, 8 warps (2m x 4n). 3-stage cp.async.
//   NPROD: 3 = ah*bh + ah*bl + al*bh; 1 = ah*bh.
//   ACT: 0 fp32 partial (no bias if SPLITK; +z-offset); 1 relu half planes
//        (WRLO: also lo); 2 softplus-split.
//   SPLITK: blockIdx.z selects K-window [z*K, (z+1)*K); lda = full row stride.
// ---------------------------------------------------------------------------
#define PLANEB 8192                     // bytes per plane (128 x 64B)
#define STAGEB (4 * PLANEB)             // Ah Al Bh Bl = 32 KB
#define NSTAGE 3

template <int ACT, int NPROD, int WRLO, int SPLITK>
__global__ __launch_bounds__(256, 2)
void mma_gemm(const __half* __restrict__ Ahg, const __half* __restrict__ Alg,
              const __half* __restrict__ Bhg, const __half* __restrict__ Blg,
              const float* __restrict__ bias,
              __half* __restrict__ Chg, __half* __restrict__ Clg,
              float* __restrict__ C, float* __restrict__ C2,
              int K, int lda, int ldc) {
    extern __shared__ __half smh[];
    __shared__ float s_bias[128];

    const int tid  = threadIdx.x;
    const int wid  = tid >> 5;
    const int lane = tid & 31;
    const int qr   = lane >> 2;
    const int qc   = lane & 3;
    const int grp  = lane >> 3;
    const int lr   = lane & 7;
    const int m_w  = (wid >> 2) * 64;
    const int n_w  = (wid & 3) * 32;
    const int row0 = blockIdx.y * 128;
    const int col0 = blockIdx.x * 128;
    const int kb   = SPLITK ? ((int)blockIdx.z * K) : 0;

    if (tid < 128) s_bias[tid] = bias[col0 + tid];

    const uint32_t smb = smem_u32(smh);

    float acc[4][4][4];
#pragma unroll
    for (int a = 0; a < 4; ++a)
#pragma unroll
        for (int b = 0; b < 4; ++b)
#pragma unroll
            for (int c = 0; c < 4; ++c) acc[a][b][c] = 0.0f;

    const int NCH  = K >> 5;
    const int r_ld = tid >> 1;
    const int q0   = (tid & 1) * 2;

    const int growA = row0 + r_ld;
    const int growB = col0 + r_ld;
    const uint32_t d_sw0 = swz(r_ld, q0);
    const uint32_t d_sw1 = swz(r_ld, q0 + 1);

    auto issue = [&](int stage, int kchunk) {
        const int k0 = kb + (kchunk << 5);
        const uint32_t sbase = smb + (uint32_t)(stage * STAGEB);
        {
            const __half* s = Ahg + (size_t)growA * lda + k0 + q0 * 8;
            cpa16(sbase + d_sw0, s);
            cpa16(sbase + d_sw1, s + 8);
        }
        if (NPROD == 3) {
            const __half* s = Alg + (size_t)growA * lda + k0 + q0 * 8;
            cpa16(sbase + (uint32_t)PLANEB + d_sw0, s);
            cpa16(sbase + (uint32_t)PLANEB + d_sw1, s + 8);
        }
        {
            const __half* s = Bhg + (size_t)growB * lda + k0 + q0 * 8;
            cpa16(sbase + (uint32_t)(2 * PLANEB) + d_sw0, s);
            cpa16(sbase + (uint32_t)(2 * PLANEB) + d_sw1, s + 8);
        }
        if (NPROD >= 2) {
            const __half* s = Blg + (size_t)growB * lda + k0 + q0 * 8;
            cpa16(sbase + (uint32_t)(3 * PLANEB) + d_sw0, s);
            cpa16(sbase + (uint32_t)(3 * PLANEB) + d_sw1, s + 8);
        }
        asm volatile("cp.async.commit_group;" ::: "memory");
    };

    // ---- prolog ----
    issue(0, 0);
    if (NCH > 1) {
        issue(1, 1);
        asm volatile("cp.async.wait_group 1;" ::: "memory");
    } else {
        asm volatile("cp.async.wait_group 0;" ::: "memory");
    }
    __syncthreads();

    for (int i = 0; i < NCH; ++i) {
        if (i + 2 < NCH) issue((i + 2) % NSTAGE, i + 2);

        const uint32_t sb = smb + (uint32_t)((i % NSTAGE) * STAGEB);
#pragma unroll
        for (int ks = 0; ks < 2; ++ks) {
            uint32_t bh[4][2], bl[4][2];
#pragma unroll
            for (int nn = 0; nn < 2; ++nn) {
                const int rB = n_w + nn * 16 + (grp >> 1) * 8 + lr;
                const int qB = ks * 2 + (grp & 1);
                const uint32_t ab = sb + (uint32_t)(2 * PLANEB) + swz(rB, qB);
                ldsm4(bh[2 * nn][0], bh[2 * nn][1],
                      bh[2 * nn + 1][0], bh[2 * nn + 1][1], ab);
                if (NPROD >= 2)
                    ldsm4(bl[2 * nn][0], bl[2 * nn][1],
                          bl[2 * nn + 1][0], bl[2 * nn + 1][1],
                          ab + (uint32_t)PLANEB);
            }
#pragma unroll
            for (int mt = 0; mt < 4; ++mt) {
                uint32_t ah[4], al[4];
                const int rA = m_w + mt * 16 + (grp & 1) * 8 + lr;
                const int qA = ks * 2 + (grp >> 1);
                const uint32_t aa = sb + swz(rA, qA);
                ldsm4(ah[0], ah[1], ah[2], ah[3], aa);
                if (NPROD == 3)
                    ldsm4(al[0], al[1], al[2], al[3], aa + (uint32_t)PLANEB);
#pragma unroll
                for (int nt = 0; nt < 4; ++nt) {
                    mma_f16(acc[mt][nt], ah, bh[nt]);
                    if (NPROD >= 2) mma_f16(acc[mt][nt], ah, bl[nt]);
                    if (NPROD == 3) mma_f16(acc[mt][nt], al, bh[nt]);
                }
            }
        }

        if (i + 1 < NCH) {
            if (i + 2 < NCH) {
                asm volatile("cp.async.wait_group 1;" ::: "memory");
            } else {
                asm volatile("cp.async.wait_group 0;" ::: "memory");
            }
            __syncthreads();
        }
    }

    // ---- epilogue ----
    float* Cz = SPLITK ? (C + (size_t)blockIdx.z * (8192ull * 128)) : C;
#pragma unroll
    for (int mt = 0; mt < 4; ++mt) {
        int r = row0 + m_w + mt * 16 + qr;
#pragma unroll
        for (int nt = 0; nt < 4; ++nt) {
            int lc = n_w + nt * 8 + 2 * qc;
            int gc = col0 + lc;
            float2 t0, t1;
            float b0v = SPLITK ? 0.0f : s_bias[lc];
            float b1v = SPLITK ? 0.0f : s_bias[lc + 1];
            t0.x = acc[mt][nt][0] + b0v;
            t0.y = acc[mt][nt][1] + b1v;
            t1.x = acc[mt][nt][2] + b0v;
            t1.y = acc[mt][nt][3] + b1v;
            if (ACT == 1) {
                t0.x = fmaxf(t0.x, 0.0f); t0.y = fmaxf(t0.y, 0.0f);
                t1.x = fmaxf(t1.x, 0.0f); t1.y = fmaxf(t1.y, 0.0f);
                if (WRLO) {
                    __half2 h2, l2;
                    split_h2(t0.x, t0.y, h2, l2);
                    *reinterpret_cast<__half2*>(&Chg[(size_t)r * ldc + gc]) = h2;
                    *reinterpret_cast<__half2*>(&Clg[(size_t)r * ldc + gc]) = l2;
                    split_h2(t1.x, t1.y, h2, l2);
                    *reinterpret_cast<__half2*>(&Chg[(size_t)(r + 8) * ldc + gc]) = h2;
                    *reinterpret_cast<__half2*>(&Clg[(size_t)(r + 8) * ldc + gc]) = l2;
                } else {
                    *reinterpret_cast<__half2*>(&Chg[(size_t)r * ldc + gc]) =
                        __floats2half2_rn(t0.x, t0.y);
                    *reinterpret_cast<__half2*>(&Chg[(size_t)(r + 8) * ldc + gc]) =
                        __floats2half2_rn(t1.x, t1.y);
                }
            } else if (ACT == 2) {
                t0.x = __fadd_rn(1e-6f, softplusf(t0.x));
                t0.y = __fadd_rn(1e-6f, softplusf(t0.y));
                t1.x = __fadd_rn(1e-6f, softplusf(t1.x));
                t1.y = __fadd_rn(1e-6f, softplusf(t1.y));
                if (gc < 2048) {
                    *reinterpret_cast<float2*>(&C [(size_t)r * 2048 + gc]) = t0;
                    *reinterpret_cast<float2*>(&C [(size_t)(r + 8) * 2048 + gc]) = t1;
                } else {
                    *reinterpret_cast<float2*>(&C2[(size_t)r * 2048 + gc - 2048]) = t0;
                    *reinterpret_cast<float2*>(&C2[(size_t)(r + 8) * 2048 + gc - 2048]) = t1;
                }
            } else {
                *reinterpret_cast<float2*>(&Cz[(size_t)r * ldc + gc]) = t0;
                *reinterpret_cast<float2*>(&Cz[(size_t)(r + 8) * ldc + gc]) = t1;
            }
        }
    }
}

// ---------------------------------------------------------------------------
// Merged prep: 9 weight transpose/split jobs + x-split blocks + bias concat.
// ---------------------------------------------------------------------------
struct PrepJobs {
    const float* W[9];
    __half* Wh[9];
    __half* Wl[9];
    int K[9], N[9], start[9], wl[9];
    int wtiles;                    // total weight-tile blocks
    const float* X;                // x to split
    __half* Xh; __half* Xl;
    int xblocks;                   // x-split blocks (256 float4 each)
    const float* hb1; const float* hb2;
    float* bh;
};

__global__ __launch_bounds__(256)
void prep_all(PrepJobs j) {
    int b = blockIdx.x;
    if (b < j.wtiles) {
        int ji = 0;
#pragma unroll
        for (int s = 1; s < 9; ++s)
            if (b >= j.start[s]) ji = s;
        const float* W = j.W[ji];
        __half* Wh = j.Wh[ji];
        __half* Wl = j.Wl[ji];
        int K = j.K[ji], N = j.N[ji];
        int wl = j.wl[ji];
        int t = b - j.start[ji];
        int ntn = N >> 5;
        int n0 = (t % ntn) << 5, k0 = (t / ntn) << 5;

        __shared__ float s[32][33];
        int tt = threadIdx.x;
        int a = tt >> 5, bb = tt & 31;
#pragma unroll
        for (int p = 0; p < 4; ++p) {
            int k = p * 8 + a;
            s[k][bb] = W[(size_t)(k0 + k) * N + n0 + bb];
        }
        __syncthreads();
#pragma unroll
        for (int p = 0; p < 4; ++p) {
            int n = p * 8 + a;
            float v = s[bb][n];
            __half h = __float2half_rn(v);
            Wh[(size_t)(n0 + n) * K + k0 + bb] = h;
            if (wl)
                Wl[(size_t)(n0 + n) * K + k0 + bb] =
                    __float2half_rn(__fadd_rn(v, -__half2float(h)));
        }
        return;
    }
    b -= j.wtiles;
    if (b < j.xblocks) {
        int t = b * 256 + threadIdx.x;
        float4 v = reinterpret_cast<const float4*>(j.X)[t];
        __half2 h0, l0, h1, l1;
        split_h2(v.x, v.y, h0, l0);
        split_h2(v.z, v.w, h1, l1);
        reinterpret_cast<__half2*>(j.Xh)[2 * t]     = h0;
        reinterpret_cast<__half2*>(j.Xh)[2 * t + 1] = h1;
        reinterpret_cast<__half2*>(j.Xl)[2 * t]     = l0;
        reinterpret_cast<__half2*>(j.Xl)[2 * t + 1] = l1;
        return;
    }
    // last block: concat head bias
    int t = threadIdx.x;
    if (t < 128) j.bh[t] = (t < 64) ? j.hb1[t] : j.hb2[t - 64];
}

// ---------------------------------------------------------------------------
// Gamma sampler: combines two K-partials + bias, then samples.
// ---------------------------------------------------------------------------
__global__ __launch_bounds__(256)
void gamma_sampler(const float* __restrict__ pre, const float* __restrict__ bh,
                   float* __restrict__ out_la, float* __restrict__ out_lb,
                   float* __restrict__ out_z, __half* __restrict__ zh) {
    int i = blockIdx.x * blockDim.x + threadIdx.x;
    if (i >= BATCHN * LATENT) return;
    int row = i >> 6, lat = i & 63;

    const float* p1 = pre + 8192ull * 128;
    float preA = (pre[row * 128 + lat]      + p1[row * 128 + lat])      + bh[lat];
    float preB = (pre[row * 128 + 64 + lat] + p1[row * 128 + 64 + lat]) + bh[64 + lat];

    float al = __fadd_rn(1e-6f, softplusf(preA));
    float be = __fadd_rn(1e-6f, softplusf(preB));

    float d  = __fadd_rn(__fadd_rn(al, 1.0f), -(1.0f / 3.0f));
    float cc = __fdiv_rn(1.0f, __fsqrt_rn(__fmul_rn(9.0f, d)));

    const float LO     = -0.99999994f;
    const float SPAN_N = 2.0f;
    const float UMIN   = 1e-7f;
    const float SPAN_U = 1.0f - 1e-7f;
    const float SQRT2  = 1.41421356f;

    float eps_s = 0.0f, u_s = 0.0f, eps0 = 0.0f, u0 = 0.0f;
    bool found = false;

#pragma unroll 1
    for (int k = 0; k < KROUNDS; ++k) {
        uint32_t idx = (uint32_t)k * GAMMA_N + (uint32_t)i;
        uint32_t bn = gamma_bits(KEY_N0, KEY_N1, idx);
        uint32_t bu = gamma_bits(KEY_U0, KEY_U1, idx);

        float un = __fadd_rn(__fmul_rn(bits_to_u01(bn), SPAN_N), LO);
        un = fmaxf(LO, un);
        float eps = __fmul_rn(SQRT2, erfinv_xla(un));

        float uu = __fadd_rn(__fmul_rn(bits_to_u01(bu), SPAN_U), UMIN);
        uu = fmaxf(UMIN, uu);

        if (k == 0) { eps0 = eps; u0 = uu; }

        float v = __fadd_rn(1.0f, __fmul_rn(cc, eps));
        bool acc = false;
        if (v > 0.0f) {
            float e2 = __fmul_rn(eps, eps);
            float squeeze = __fadd_rn(1.0f, -__fmul_rn(__fmul_rn(0.0331f, e2), e2));
            if (uu < squeeze) {
                acc = true;
            } else {
                float v3 = __fmul_rn(__fmul_rn(v, v), v);
                float inner = __fadd_rn(__fadd_rn(1.0f, -v3), logf(v3));
                float rhs = __fadd_rn(__fmul_rn(__fmul_rn(0.5f, eps), eps),
                                      __fmul_rn(d, inner));
                if (logf(uu) < rhs) acc = true;
            }
        }
        if (acc) { eps_s = eps; u_s = uu; found = true; break; }
    }
    if (!found) { eps_s = eps0; u_s = u0; }

    float v1 = __fadd_rn(1.0f, __fmul_rn(cc, eps_s));
    float vs = __fmul_rn(v1, __fmul_rn(v1, v1));
    float t1 = logf(__fadd_rn(__fmul_rn(d, vs), 1e-6f));
    float t2 = __fdiv_rn(logf(__fadd_rn(u_s, 1e-6f)), __fadd_rn(al, 1e-6f));
    float z  = __fdiv_rn(expf(__fadd_rn(t1, t2)), __fadd_rn(be, 1e-6f));

    out_la[i] = al;
    out_lb[i] = be;
    out_z[i]  = z;
    zh[i] = __float2half_rn(z);
}

// ---------------------------------------------------------------------------
// Launch
// ---------------------------------------------------------------------------
extern "C" void kernel_launch(void* const* d_in, const int* in_sizes, int n_in,
                              void* d_out, int out_size) {
    (void)in_sizes; (void)n_in; (void)out_size;

    const float* x    = (const float*)d_in[0];
    const float* f1w  = (const float*)d_in[1];
    const float* f1b  = (const float*)d_in[2];
    const float* f2w  = (const float*)d_in[3];
    const float* f2b  = (const float*)d_in[4];
    const float* f3w  = (const float*)d_in[5];
    const float* f3b  = (const float*)d_in[6];
    const float* f41w = (const float*)d_in[7];
    const float* f41b = (const float*)d_in[8];
    const float* f42w = (const float*)d_in[9];
    const float* f42b = (const float*)d_in[10];
    const float* f4w  = (const float*)d_in[11];
    const float* f4b  = (const float*)d_in[12];
    const float* f5w  = (const float*)d_in[13];
    const float* f5b  = (const float*)d_in[14];
    const float* f6w  = (const float*)d_in[15];
    const float* f6b  = (const float*)d_in[16];
    const float* f7w  = (const float*)d_in[17];
    const float* f7b  = (const float*)d_in[18];

    float* out = (float*)d_out;
    const size_t OFF_BE = 8192ull * 2048;
    const size_t OFF_LA = 2 * OFF_BE;
    const size_t OFF_LB = OFF_LA + 524288;
    const size_t OFF_Z  = OFF_LB + 524288;

    __half *xh, *xl, *b0h, *b0l, *b1h, *b1l, *zh, *wh, *wl;
    float *pre, *bh;
    cudaGetSymbolAddress((void**)&xh,  g_xh);
    cudaGetSymbolAddress((void**)&xl,  g_xl);
    cudaGetSymbolAddress((void**)&b0h, g_b0h);
    cudaGetSymbolAddress((void**)&b0l, g_b0l);
    cudaGetSymbolAddress((void**)&b1h, g_b1h);
    cudaGetSymbolAddress((void**)&b1l, g_b1l);
    cudaGetSymbolAddress((void**)&zh,  g_zh);
    cudaGetSymbolAddress((void**)&wh,  g_wh);
    cudaGetSymbolAddress((void**)&wl,  g_wl);
    cudaGetSymbolAddress((void**)&pre, g_pre);
    cudaGetSymbolAddress((void**)&bh,  g_bh);

    constexpr int DYN = NSTAGE * STAGEB;   // 98304 bytes
    cudaFuncSetAttribute((const void*)mma_gemm<0, 3, 0, 1>, cudaFuncAttributeMaxDynamicSharedMemorySize, DYN);
    cudaFuncSetAttribute((const void*)mma_gemm<1, 3, 1, 0>, cudaFuncAttributeMaxDynamicSharedMemorySize, DYN);
    cudaFuncSetAttribute((const void*)mma_gemm<1, 1, 0, 0>, cudaFuncAttributeMaxDynamicSharedMemorySize, DYN);
    cudaFuncSetAttribute((const void*)mma_gemm<2, 1, 0, 0>, cudaFuncAttributeMaxDynamicSharedMemorySize, DYN);

    // ---- single merged prep launch ----
    PrepJobs jp = {};
    int st = 0;
    auto add = [&](int idx, const float* W, uint32_t off, int K, int N, int wlf) {
        jp.W[idx] = W; jp.Wh[idx] = wh + off; jp.Wl[idx] = wl + off;
        jp.K[idx] = K; jp.N[idx] = N; jp.start[idx] = st; jp.wl[idx] = wlf;
        st += (N >> 5) * (K >> 5);
    };
    add(0, f1w,  OW1, 2048, 1024, 1);
    add(1, f2w,  OW2, 1024, 1024, 1);
    add(2, f3w,  OW3, 1024, 2048, 1);
    add(3, f41w, OWH, 2048, 64,   1);
    add(4, f42w, OWH + 64 * 2048, 2048, 64, 1);
    add(5, f4w,  OW4, 64,   2048, 0);
    add(6, f5w,  OW5, 2048, 1024, 0);
    add(7, f6w,  OW6, 1024, 1024, 0);
    add(8, f7w,  OW7, 1024, 4096, 0);
    jp.wtiles = st;
    jp.X = x; jp.Xh = xh; jp.Xl = xl;
    jp.xblocks = (8192 * 2048 / 4) / 256;   // 16384
    jp.hb1 = f41b; jp.hb2 = f42b; jp.bh = bh;
    prep_all<<<jp.wtiles + jp.xblocks + 1, 256>>>(jp);

    // ---- encoder (3-product, exact-class) ----
    mma_gemm<1, 3, 1, 0><<<dim3( 8, 64), 256, DYN>>>(xh,  xl,  wh + OW1, wl + OW1, f1b, b0h, b0l, nullptr, nullptr, 2048, 2048, 1024);
    mma_gemm<1, 3, 1, 0><<<dim3( 8, 64), 256, DYN>>>(b0h, b0l, wh + OW2, wl + OW2, f2b, b1h, b1l, nullptr, nullptr, 1024, 1024, 1024);
    mma_gemm<1, 3, 1, 0><<<dim3(16, 64), 256, DYN>>>(b1h, b1l, wh + OW3, wl + OW3, f3b, b0h, b0l, nullptr, nullptr, 1024, 1024, 2048);
    // fused heads, split-K=2: partials (no bias) -> pre[0], pre[1M]
    mma_gemm<0, 3, 0, 1><<<dim3(1, 64, 2), 256, DYN>>>(b0h, b0l, wh + OWH, wl + OWH, bh, nullptr, nullptr, pre, nullptr, 1024, 2048, 128);
    // ---- gamma reparameterization (combines partials + bias) ----
    gamma_sampler<<<(BATCHN * LATENT) / 256, 256>>>(
        pre, bh, out + OFF_LA, out + OFF_LB, out + OFF_Z, zh);
    // ---- decoder (1-product: fp16 weights x fp16 activations) ----
    mma_gemm<1, 1, 0, 0><<<dim3(16, 64), 256, DYN>>>(zh,  nullptr, wh + OW4, nullptr, f4b, b1h, nullptr, nullptr, nullptr, 64, 64, 2048);
    mma_gemm<1, 1, 0, 0><<<dim3( 8, 64), 256, DYN>>>(b1h, nullptr, wh + OW5, nullptr, f5b, b0h, nullptr, nullptr, nullptr, 2048, 2048, 1024);
    mma_gemm<1, 1, 0, 0><<<dim3( 8, 64), 256, DYN>>>(b0h, nullptr, wh + OW6, nullptr, f6b, b1h, nullptr, nullptr, nullptr, 1024, 1024, 1024);
    // fc7 with fused softplus-split epilogue -> fp32 outputs
    mma_gemm<2, 1, 0, 0><<<dim3(32, 64), 256, DYN>>>(b1h, nullptr, wh + OW7, nullptr, f7b, nullptr, nullptr, out, out + OFF_BE, 1024, 1024, 2048);
}